// round 14
// baseline (speedup 1.0000x reference)
#include <cuda_runtime.h>
#include <cuda_fp16.h>
#include <mma.h>
#include <cstdint>

using namespace nvcuda;

#define N_NODES_MAX 100032
#define M_PAD 100096         // GEMM row padding (zero rows beyond M)
#define FDIM 256
#define ROW_CAP 128          // max degree capacity (Poisson(32); max ~59 expected)

// ---- device scratch (static .bss, no runtime alloc) ----
__device__ __half g_a_h[(size_t)M_PAD * FDIM];                   // A in fp16 (51 MB)
__device__ __half g_b_h[FDIM * FDIM];                            // B in fp16 (128 KB)
__device__ __half g_support_h[(size_t)M_PAD * FDIM];             // X @ W in fp16 (51 MB)
__device__ int    g_cursor[N_NODES_MAX];                         // zero-init; gather re-zeros
__device__ int2   g_pedge[(size_t)N_NODES_MAX * ROW_CAP];        // padded {col,val} buckets (102 MB)

static __device__ __forceinline__ uint32_t smem_u32(const void* p) {
    return (uint32_t)__cvta_generic_to_shared(p);
}
#define CP_ASYNC16(dst, src) \
    asm volatile("cp.async.cg.shared.global [%0], [%1], 16;" :: "r"(dst), "l"(src))
#define CP_COMMIT() asm volatile("cp.async.commit_group;")
#define CP_WAIT(n)  asm volatile("cp.async.wait_group %0;" :: "n"(n))

// smem layout constants (3-stage)
#define AS_STAGE_BYTES 10240      // 128 rows x 80 B (40 halves)
#define BS_STAGE_BYTES 8704       // 32 rows x 272 B (136 halves)
#define STAGE_BYTES (AS_STAGE_BYTES + BS_STAGE_BYTES)   // 18944
#define NSTAGE 3
#define GEMM_SMEM (STAGE_BYTES * NSTAGE)                // 56832

// ---------------------------------------------------------------------------
// fp32 -> fp16 convert for A (all chunks) and B (first nb8 chunks)
// ---------------------------------------------------------------------------
__global__ __launch_bounds__(256) void convert_kernel(const float* __restrict__ a_src,
                                                      __half* __restrict__ a_dst, int na8,
                                                      const float* __restrict__ b_src,
                                                      __half* __restrict__ b_dst, int nb8) {
    int i = blockIdx.x * 256 + threadIdx.x;
    auto conv8 = [](const float* s, __half* d, int idx) {
        const float4* s4 = reinterpret_cast<const float4*>(s);
        float4 v0 = __ldg(&s4[idx * 2]);
        float4 v1 = __ldg(&s4[idx * 2 + 1]);
        __half2 h0 = __floats2half2_rn(v0.x, v0.y);
        __half2 h1 = __floats2half2_rn(v0.z, v0.w);
        __half2 h2 = __floats2half2_rn(v1.x, v1.y);
        __half2 h3 = __floats2half2_rn(v1.z, v1.w);
        uint4 pack;
        pack.x = *reinterpret_cast<uint32_t*>(&h0);
        pack.y = *reinterpret_cast<uint32_t*>(&h1);
        pack.z = *reinterpret_cast<uint32_t*>(&h2);
        pack.w = *reinterpret_cast<uint32_t*>(&h3);
        reinterpret_cast<uint4*>(d)[idx] = pack;
    };
    if (i < na8) conv8(a_src, a_dst, i);
    if (i < nb8) conv8(b_src, b_dst, i);
}

// ---------------------------------------------------------------------------
// fp16 WMMA GEMM, 3-stage cp.async pipeline, 1 syncthreads per k-iter.
// BM=128 BN=128 BK=32, 256 threads (8 warps: 4m x 2n), warp tile 32x64.
// ---------------------------------------------------------------------------
__global__ __launch_bounds__(256) void gemm_cp_kernel(int M) {
    extern __shared__ char smem_dyn[];

    const int tid = threadIdx.x;
    const int wid = tid >> 5;
    const int lane = tid & 31;
    const int warp_m = wid & 3;
    const int warp_n = wid >> 2;
    const int block_m = blockIdx.x * 128;
    const int block_n = blockIdx.y * 128;

    // A: 128 rows x 64B = 512 x 16B chunks; thread t -> chunks t, t+256
    const int a_row0 = tid >> 2;        // 0..63 (+64)
    const int a_off = tid & 3;
    // B: 32 rows x 256B = 512 x 16B chunks
    const int b_row0 = tid >> 4;        // 0..15 (+16)
    const int b_off = tid & 15;

    const uint32_t smem_base = smem_u32(smem_dyn);

    wmma::fragment<wmma::accumulator, 16, 16, 16, float> c[2][4];
#pragma unroll
    for (int i = 0; i < 2; i++)
#pragma unroll
        for (int j = 0; j < 4; j++) wmma::fill_fragment(c[i][j], 0.0f);

    auto issue_tile = [&](int k0, int s) {
        const uint32_t as_s = smem_base + s * STAGE_BYTES;
        const uint32_t bs_s = as_s + AS_STAGE_BYTES;
#pragma unroll
        for (int i = 0; i < 2; i++) {
            int row = a_row0 + i * 64;
            const __half* src = g_a_h + (size_t)(block_m + row) * FDIM + k0 + a_off * 8;
            CP_ASYNC16(as_s + row * 80 + a_off * 16, src);
        }
#pragma unroll
        for (int i = 0; i < 2; i++) {
            int row = b_row0 + i * 16;
            const __half* src = g_b_h + (size_t)(k0 + row) * FDIM + block_n + b_off * 8;
            CP_ASYNC16(bs_s + row * 272 + b_off * 16, src);
        }
        CP_COMMIT();
    };

    issue_tile(0, 0);
    issue_tile(32, 1);

#pragma unroll
    for (int it = 0; it < 8; it++) {
        if (it == 7) { CP_WAIT(0); } else { CP_WAIT(1); }
        __syncthreads();                       // all warps done computing stage it-1
        if (it + 2 < 8) issue_tile((it + 2) * 32, (it + 2) % NSTAGE);

        const __half* as = reinterpret_cast<const __half*>(smem_dyn + (it % NSTAGE) * STAGE_BYTES);
        const __half* bs = reinterpret_cast<const __half*>(smem_dyn + (it % NSTAGE) * STAGE_BYTES + AS_STAGE_BYTES);

#pragma unroll
        for (int ks = 0; ks < 2; ks++) {
            wmma::fragment<wmma::matrix_a, 16, 16, 16, __half, wmma::row_major> a[2];
            wmma::fragment<wmma::matrix_b, 16, 16, 16, __half, wmma::row_major> b[4];
#pragma unroll
            for (int i = 0; i < 2; i++)
                wmma::load_matrix_sync(a[i], as + (warp_m * 32 + i * 16) * 40 + ks * 16, 40);
#pragma unroll
            for (int j = 0; j < 4; j++)
                wmma::load_matrix_sync(b[j], bs + (ks * 16) * 136 + warp_n * 64 + j * 16, 136);
#pragma unroll
            for (int i = 0; i < 2; i++)
#pragma unroll
                for (int j = 0; j < 4; j++)
                    wmma::mma_sync(c[i][j], a[i], b[j], c[i][j]);
        }
    }

    // Epilogue: stage fragments in smem (reuse stage memory), fp16 store.
    __syncthreads();
    float* cst = reinterpret_cast<float*>(smem_dyn) + wid * 320;  // 16x20 per warp
#pragma unroll
    for (int i = 0; i < 2; i++) {
#pragma unroll
        for (int j = 0; j < 4; j++) {
            __syncwarp();
            wmma::store_matrix_sync(cst, c[i][j], 20, wmma::mem_row_major);
            __syncwarp();
            int r = lane >> 1;
            int half8 = (lane & 1) * 8;
            int grow = block_m + warp_m * 32 + i * 16 + r;
            int gcol = block_n + warp_n * 64 + j * 16 + half8;
            if (grow < M) {
                const float* src = cst + r * 20 + half8;
                __half2 h0 = __floats2half2_rn(src[0], src[1]);
                __half2 h1 = __floats2half2_rn(src[2], src[3]);
                __half2 h2 = __floats2half2_rn(src[4], src[5]);
                __half2 h3 = __floats2half2_rn(src[6], src[7]);
                uint4 pack;
                pack.x = *reinterpret_cast<uint32_t*>(&h0);
                pack.y = *reinterpret_cast<uint32_t*>(&h1);
                pack.z = *reinterpret_cast<uint32_t*>(&h2);
                pack.w = *reinterpret_cast<uint32_t*>(&h3);
                *reinterpret_cast<uint4*>(g_support_h + (size_t)grow * FDIM + gcol) = pack;
            }
        }
    }
}

// ---------------------------------------------------------------------------
// Direct padded bucketing: pedge[r*ROW_CAP + pos] = {col, val}; cursor = degree.
// ---------------------------------------------------------------------------
__global__ __launch_bounds__(256) void bucket_kernel(const int* __restrict__ rows,
                                                     const int* __restrict__ cols,
                                                     const float* __restrict__ vals, int E) {
    const int tid = blockIdx.x * 256 + threadIdx.x;
    const int e4 = E >> 2;
    if (tid < e4) {
        int4 r = __ldg(&reinterpret_cast<const int4*>(rows)[tid]);
        int4 c = __ldg(&reinterpret_cast<const int4*>(cols)[tid]);
        float4 v = __ldg(&reinterpret_cast<const float4*>(vals)[tid]);
        int p0 = atomicAdd(&g_cursor[r.x], 1);
        int p1 = atomicAdd(&g_cursor[r.y], 1);
        int p2 = atomicAdd(&g_cursor[r.z], 1);
        int p3 = atomicAdd(&g_cursor[r.w], 1);
        g_pedge[(size_t)r.x * ROW_CAP + p0] = make_int2(c.x, __float_as_int(v.x));
        g_pedge[(size_t)r.y * ROW_CAP + p1] = make_int2(c.y, __float_as_int(v.y));
        g_pedge[(size_t)r.z * ROW_CAP + p2] = make_int2(c.z, __float_as_int(v.z));
        g_pedge[(size_t)r.w * ROW_CAP + p3] = make_int2(c.w, __float_as_int(v.w));
    }
    int t = (e4 << 2) + tid;
    if (t >= (e4 << 2) && t < E && tid < 4) {
        int r = __ldg(&rows[t]);
        int pos = atomicAdd(&g_cursor[r], 1);
        g_pedge[(size_t)r * ROW_CAP + pos] = make_int2(__ldg(&cols[t]), __float_as_int(__ldg(&vals[t])));
    }
}

// ---------------------------------------------------------------------------
// Pull-mode SpMM: one warp per row; lane owns 8 halfs (16B load).
// ---------------------------------------------------------------------------
__global__ __launch_bounds__(256) void gather_kernel(const float* __restrict__ bias,
                                                     float* __restrict__ out, int M) {
    const int warp = (blockIdx.x * 256 + threadIdx.x) >> 5;
    const int lane = threadIdx.x & 31;
    if (warp >= M) return;
    const int r = warp;

    const int deg = g_cursor[r];

    const float4* bias4 = reinterpret_cast<const float4*>(bias);
    float4 a0 = bias4[lane * 2];
    float4 a1 = bias4[lane * 2 + 1];

    const uint4* sup = reinterpret_cast<const uint4*>(g_support_h);
    const int2* edges = g_pedge + (size_t)r * ROW_CAP;

    int2 nxt = (deg > 0) ? __ldg(&edges[0]) : make_int2(0, 0);
    for (int j = 0; j < deg; j++) {
        const int2 cur = nxt;
        if (j + 1 < deg) nxt = __ldg(&edges[j + 1]);
        const float v = __int_as_float(cur.y);
        uint4 h = __ldg(&sup[(size_t)cur.x * 32 + lane]);

        float2 f0 = __half22float2(*reinterpret_cast<__half2*>(&h.x));
        float2 f1 = __half22float2(*reinterpret_cast<__half2*>(&h.y));
        float2 f2 = __half22float2(*reinterpret_cast<__half2*>(&h.z));
        float2 f3 = __half22float2(*reinterpret_cast<__half2*>(&h.w));

        a0.x = fmaf(v, f0.x, a0.x);
        a0.y = fmaf(v, f0.y, a0.y);
        a0.z = fmaf(v, f1.x, a0.z);
        a0.w = fmaf(v, f1.y, a0.w);
        a1.x = fmaf(v, f2.x, a1.x);
        a1.y = fmaf(v, f2.y, a1.y);
        a1.z = fmaf(v, f3.x, a1.z);
        a1.w = fmaf(v, f3.y, a1.w);
    }

    if (lane == 0) g_cursor[r] = 0;  // restore zero invariant for next graph replay

    float4* out4 = reinterpret_cast<float4*>(out);
    out4[(size_t)r * 64 + lane * 2] = a0;
    out4[(size_t)r * 64 + lane * 2 + 1] = a1;
}

extern "C" void kernel_launch(void* const* d_in, const int* in_sizes, int n_in,
                              void* d_out, int out_size) {
    const float* input  = (const float*)d_in[0];
    const float* weight = (const float*)d_in[1];
    const float* bias   = (const float*)d_in[2];
    const int*   e_rows = (const int*)d_in[3];
    const int*   e_cols = (const int*)d_in[4];
    const float* e_vals = (const float*)d_in[5];
    float* out = (float*)d_out;

    const int M = in_sizes[0] / FDIM;
    const int E = in_sizes[3];
    const int e4 = E >> 2;
    const int eblocks = (e4 + 255) / 256;

    // Lazily-created side stream + events + attribute (host objects / one-time).
    static cudaStream_t s_side = nullptr;
    static cudaEvent_t  ev_fork = nullptr, ev_join = nullptr;
    if (s_side == nullptr) {
        cudaStreamCreateWithFlags(&s_side, cudaStreamNonBlocking);
        cudaEventCreateWithFlags(&ev_fork, cudaEventDisableTiming);
        cudaEventCreateWithFlags(&ev_join, cudaEventDisableTiming);
        cudaFuncSetAttribute(gemm_cp_kernel,
                             cudaFuncAttributeMaxDynamicSharedMemorySize, GEMM_SMEM);
    }

    // Fork: bucket runs concurrently with convert+GEMM (independent data).
    cudaEventRecord(ev_fork, 0);
    cudaStreamWaitEvent(s_side, ev_fork, 0);
    bucket_kernel<<<eblocks, 256, 0, s_side>>>(e_rows, e_cols, e_vals, E);
    cudaEventRecord(ev_join, s_side);

    // Main stream: convert A+B (one launch), then GEMM.
    __half* a_h;  cudaGetSymbolAddress((void**)&a_h, g_a_h);
    __half* b_h;  cudaGetSymbolAddress((void**)&b_h, g_b_h);
    const int na8 = (M * FDIM) / 8;
    const int nb8 = (FDIM * FDIM) / 8;
    convert_kernel<<<(na8 + 255) / 256, 256>>>(input, a_h, na8, weight, b_h, nb8);

    dim3 ggrid((M + 127) / 128, FDIM / 128);
    gemm_cp_kernel<<<ggrid, 256, GEMM_SMEM>>>(M);

    // Join: gather needs both GEMM (support) and bucket (edges).
    cudaStreamWaitEvent(0, ev_join, 0);
    gather_kernel<<<(M * 32 + 255) / 256, 256>>>(bias, out, M);
}

// round 15
// speedup vs baseline: 1.0420x; 1.0420x over previous
#include <cuda_runtime.h>
#include <cuda_fp16.h>
#include <mma.h>
#include <cstdint>

using namespace nvcuda;

#define N_NODES_MAX 100032
#define M_PAD 100096
#define FDIM 256
#define ROW_CAP 128

// ---- device scratch (static .bss, no runtime alloc) ----
__device__ __half g_a_h[(size_t)M_PAD * FDIM];                   // A in fp16 (51 MB)
__device__ __half g_b_h[FDIM * FDIM];                            // B in fp16 (128 KB)
__device__ __half g_support_h[(size_t)M_PAD * FDIM];             // X @ W in fp16 (51 MB)
__device__ int    g_cursor[N_NODES_MAX];                         // zero-init; gather re-zeros
__device__ int2   g_pedge[(size_t)N_NODES_MAX * ROW_CAP];        // padded {col,val} buckets (102 MB)

static __device__ __forceinline__ uint32_t smem_u32(const void* p) {
    return (uint32_t)__cvta_generic_to_shared(p);
}
#define CP_ASYNC16(dst, src) \
    asm volatile("cp.async.cg.shared.global [%0], [%1], 16;" :: "r"(dst), "l"(src))
#define CP_COMMIT() asm volatile("cp.async.commit_group;")
#define CP_WAIT(n)  asm volatile("cp.async.wait_group %0;" :: "n"(n))

// ---------------------------------------------------------------------------
// Fused: bucket edges (atomic-latency-bound) + fp32->fp16 convert (DRAM-bound).
// Complementary resources -> warp-level interleave hides atomic latency.
// Grid: ceil(na8/256). Thread i: bucket edge-chunk i (if i<e4), convert A chunk i,
// convert B chunk i (if i<nb8), plus edge tail.
// ---------------------------------------------------------------------------
__global__ __launch_bounds__(256) void fused_cb_kernel(const int* __restrict__ rows,
                                                       const int* __restrict__ cols,
                                                       const float* __restrict__ vals, int E,
                                                       const float* __restrict__ a_src, int na8,
                                                       const float* __restrict__ b_src, int nb8) {
    const int i = blockIdx.x * 256 + threadIdx.x;
    const int e4 = E >> 2;

    // --- bucket part (atomics issued first; latency overlaps convert loads) ---
    if (i < e4) {
        int4 r = __ldg(&reinterpret_cast<const int4*>(rows)[i]);
        int4 c = __ldg(&reinterpret_cast<const int4*>(cols)[i]);
        float4 v = __ldg(&reinterpret_cast<const float4*>(vals)[i]);
        int p0 = atomicAdd(&g_cursor[r.x], 1);
        int p1 = atomicAdd(&g_cursor[r.y], 1);
        int p2 = atomicAdd(&g_cursor[r.z], 1);
        int p3 = atomicAdd(&g_cursor[r.w], 1);
        g_pedge[(size_t)r.x * ROW_CAP + p0] = make_int2(c.x, __float_as_int(v.x));
        g_pedge[(size_t)r.y * ROW_CAP + p1] = make_int2(c.y, __float_as_int(v.y));
        g_pedge[(size_t)r.z * ROW_CAP + p2] = make_int2(c.z, __float_as_int(v.z));
        g_pedge[(size_t)r.w * ROW_CAP + p3] = make_int2(c.w, __float_as_int(v.w));
    }
    {   // edge tail (E not multiple of 4)
        int t = (e4 << 2) + i;
        if (t >= (e4 << 2) && t < E && i < 4) {
            int r = __ldg(&rows[t]);
            int pos = atomicAdd(&g_cursor[r], 1);
            g_pedge[(size_t)r * ROW_CAP + pos] = make_int2(__ldg(&cols[t]), __float_as_int(__ldg(&vals[t])));
        }
    }

    // --- convert part ---
    auto conv8 = [](const float* s, __half* d, int idx) {
        const float4* s4 = reinterpret_cast<const float4*>(s);
        float4 v0 = __ldg(&s4[idx * 2]);
        float4 v1 = __ldg(&s4[idx * 2 + 1]);
        __half2 h0 = __floats2half2_rn(v0.x, v0.y);
        __half2 h1 = __floats2half2_rn(v0.z, v0.w);
        __half2 h2 = __floats2half2_rn(v1.x, v1.y);
        __half2 h3 = __floats2half2_rn(v1.z, v1.w);
        uint4 pack;
        pack.x = *reinterpret_cast<uint32_t*>(&h0);
        pack.y = *reinterpret_cast<uint32_t*>(&h1);
        pack.z = *reinterpret_cast<uint32_t*>(&h2);
        pack.w = *reinterpret_cast<uint32_t*>(&h3);
        reinterpret_cast<uint4*>(d)[idx] = pack;
    };
    if (i < na8) conv8(a_src, g_a_h, i);
    if (i < nb8) conv8(b_src, g_b_h, i);
}

// ---------------------------------------------------------------------------
// fp16 WMMA GEMM with cp.async 2-stage pipeline (R13 version, measured 59us).
// BM=128 BN=128 BK=32, 256 threads (8 warps: 4m x 2n), warp tile 32x64.
// ---------------------------------------------------------------------------
__global__ __launch_bounds__(256) void gemm_cp_kernel(int M) {
    __shared__ __half As[2][128][40];
    __shared__ __half Bs[2][32][136];
    __shared__ float  Cstage[8][16][20];

    const int tid = threadIdx.x;
    const int wid = tid >> 5;
    const int lane = tid & 31;
    const int warp_m = wid & 3;
    const int warp_n = wid >> 2;
    const int block_m = blockIdx.x * 128;
    const int block_n = blockIdx.y * 128;

    const int a_row0 = tid >> 2;
    const int a_off = tid & 3;
    const int b_row0 = tid >> 4;
    const int b_off = tid & 15;

    const uint32_t as_base = smem_u32(&As[0][0][0]);
    const uint32_t bs_base = smem_u32(&Bs[0][0][0]);

    wmma::fragment<wmma::accumulator, 16, 16, 16, float> c[2][4];
#pragma unroll
    for (int i = 0; i < 2; i++)
#pragma unroll
        for (int j = 0; j < 4; j++) wmma::fill_fragment(c[i][j], 0.0f);

    auto issue_tile = [&](int k0, int b) {
#pragma unroll
        for (int i = 0; i < 2; i++) {
            int row = a_row0 + i * 64;
            const __half* src = g_a_h + (size_t)(block_m + row) * FDIM + k0 + a_off * 8;
            CP_ASYNC16(as_base + b * 10240 + row * 80 + a_off * 16, src);
        }
#pragma unroll
        for (int i = 0; i < 2; i++) {
            int row = b_row0 + i * 16;
            const __half* src = g_b_h + (size_t)(k0 + row) * FDIM + block_n + b_off * 8;
            CP_ASYNC16(bs_base + b * 8704 + row * 272 + b_off * 16, src);
        }
        CP_COMMIT();
    };

    issue_tile(0, 0);

    int buf = 0;
    for (int k0 = 0; k0 < FDIM; k0 += 32) {
        const bool has_next = (k0 + 32 < FDIM);
        if (has_next) {
            issue_tile(k0 + 32, buf ^ 1);
            CP_WAIT(1);
        } else {
            CP_WAIT(0);
        }
        __syncthreads();

#pragma unroll
        for (int ks = 0; ks < 2; ks++) {
            wmma::fragment<wmma::matrix_a, 16, 16, 16, __half, wmma::row_major> a[2];
            wmma::fragment<wmma::matrix_b, 16, 16, 16, __half, wmma::row_major> b[4];
#pragma unroll
            for (int i = 0; i < 2; i++)
                wmma::load_matrix_sync(a[i], &As[buf][warp_m * 32 + i * 16][ks * 16], 40);
#pragma unroll
            for (int j = 0; j < 4; j++)
                wmma::load_matrix_sync(b[j], &Bs[buf][ks * 16][warp_n * 64 + j * 16], 136);
#pragma unroll
            for (int i = 0; i < 2; i++)
#pragma unroll
                for (int j = 0; j < 4; j++)
                    wmma::mma_sync(c[i][j], a[i], b[j], c[i][j]);
        }
        __syncthreads();
        buf ^= 1;
    }

#pragma unroll
    for (int i = 0; i < 2; i++) {
#pragma unroll
        for (int j = 0; j < 4; j++) {
            __syncwarp();
            wmma::store_matrix_sync(&Cstage[wid][0][0], c[i][j], 20, wmma::mem_row_major);
            __syncwarp();
            int r = lane >> 1;
            int half8 = (lane & 1) * 8;
            int grow = block_m + warp_m * 32 + i * 16 + r;
            int gcol = block_n + warp_n * 64 + j * 16 + half8;
            if (grow < M) {
                const float* src = &Cstage[wid][r][half8];
                __half2 h0 = __floats2half2_rn(src[0], src[1]);
                __half2 h1 = __floats2half2_rn(src[2], src[3]);
                __half2 h2 = __floats2half2_rn(src[4], src[5]);
                __half2 h3 = __floats2half2_rn(src[6], src[7]);
                uint4 pack;
                pack.x = *reinterpret_cast<uint32_t*>(&h0);
                pack.y = *reinterpret_cast<uint32_t*>(&h1);
                pack.z = *reinterpret_cast<uint32_t*>(&h2);
                pack.w = *reinterpret_cast<uint32_t*>(&h3);
                *reinterpret_cast<uint4*>(g_support_h + (size_t)grow * FDIM + gcol) = pack;
            }
        }
    }
}

// ---------------------------------------------------------------------------
// Pull-mode SpMM: one warp per row; lane owns 8 halfs; 2-edge unrolled loop
// (two independent 16B sup loads in flight per iteration).
// ---------------------------------------------------------------------------
__global__ __launch_bounds__(256) void gather_kernel(const float* __restrict__ bias,
                                                     float* __restrict__ out, int M) {
    const int warp = (blockIdx.x * 256 + threadIdx.x) >> 5;
    const int lane = threadIdx.x & 31;
    if (warp >= M) return;
    const int r = warp;

    const int deg = g_cursor[r];

    const float4* bias4 = reinterpret_cast<const float4*>(bias);
    float4 a0 = bias4[lane * 2];
    float4 a1 = bias4[lane * 2 + 1];

    const uint4* sup = reinterpret_cast<const uint4*>(g_support_h);
    const int2* edges = g_pedge + (size_t)r * ROW_CAP;

    auto fma8 = [&](float v, const uint4& h) {
        float2 f0 = __half22float2(*reinterpret_cast<const __half2*>(&h.x));
        float2 f1 = __half22float2(*reinterpret_cast<const __half2*>(&h.y));
        float2 f2 = __half22float2(*reinterpret_cast<const __half2*>(&h.z));
        float2 f3 = __half22float2(*reinterpret_cast<const __half2*>(&h.w));
        a0.x = fmaf(v, f0.x, a0.x);
        a0.y = fmaf(v, f0.y, a0.y);
        a0.z = fmaf(v, f1.x, a0.z);
        a0.w = fmaf(v, f1.y, a0.w);
        a1.x = fmaf(v, f2.x, a1.x);
        a1.y = fmaf(v, f2.y, a1.y);
        a1.z = fmaf(v, f3.x, a1.z);
        a1.w = fmaf(v, f3.y, a1.w);
    };

    int j = 0;
    for (; j + 2 <= deg; j += 2) {
        int2 e0 = __ldg(&edges[j]);
        int2 e1 = __ldg(&edges[j + 1]);
        uint4 h0 = __ldg(&sup[(size_t)e0.x * 32 + lane]);
        uint4 h1 = __ldg(&sup[(size_t)e1.x * 32 + lane]);
        fma8(__int_as_float(e0.y), h0);
        fma8(__int_as_float(e1.y), h1);
    }
    if (j < deg) {
        int2 e0 = __ldg(&edges[j]);
        uint4 h0 = __ldg(&sup[(size_t)e0.x * 32 + lane]);
        fma8(__int_as_float(e0.y), h0);
    }

    if (lane == 0) g_cursor[r] = 0;  // restore zero invariant for next graph replay

    float4* out4 = reinterpret_cast<float4*>(out);
    out4[(size_t)r * 64 + lane * 2] = a0;
    out4[(size_t)r * 64 + lane * 2 + 1] = a1;
}

extern "C" void kernel_launch(void* const* d_in, const int* in_sizes, int n_in,
                              void* d_out, int out_size) {
    const float* input  = (const float*)d_in[0];
    const float* weight = (const float*)d_in[1];
    const float* bias   = (const float*)d_in[2];
    const int*   e_rows = (const int*)d_in[3];
    const int*   e_cols = (const int*)d_in[4];
    const float* e_vals = (const float*)d_in[5];
    float* out = (float*)d_out;

    const int M = in_sizes[0] / FDIM;
    const int E = in_sizes[3];
    const int na8 = (M * FDIM) / 8;
    const int nb8 = (FDIM * FDIM) / 8;

    // 1) fused bucket + fp32->fp16 convert (complementary resources)
    fused_cb_kernel<<<(na8 + 255) / 256, 256>>>(e_rows, e_cols, e_vals, E,
                                                input, na8, weight, nb8);

    // 2) fp16 GEMM (cp.async pipeline)
    dim3 ggrid((M + 127) / 128, FDIM / 128);
    gemm_cp_kernel<<<ggrid, 256>>>(M);

    // 3) pull-mode SpMM + bias (also resets cursors)
    gather_kernel<<<(M * 32 + 255) / 256, 256>>>(bias, out, M);
}